// round 13
// baseline (speedup 1.0000x reference)
#include <cuda_runtime.h>
#include <cstdint>
#include <cstddef>

// ---------------- device scratch (zero-initialized; consume-and-clear keeps it zeroed) ----------------
#define MAX_N 262144
__device__ float    g_v[128];           // proj_w @ w_st
__device__ float    g_U[16];            // user_out[b] + b_u + b_st
__device__ float    g_c;                // proj_b · w_st
__device__ float    g_delta[1 << 20];   // per-(b,n) scattered correction
__device__ unsigned g_flag[MAX_N];      // per-n batch bitmask

__device__ __forceinline__ float warp_sum(float p) {
    #pragma unroll
    for (int off = 16; off; off >>= 1)
        p += __shfl_xor_sync(0xffffffffu, p, off);
    return p;
}

// 8 independent 32-lane reductions in 9 shuffles. a[i] = per-lane partial of row i.
// Result: every lane holds sum of row = ((lane>>4)&1)*4 + ((lane>>3)&1)*2 + ((lane>>2)&1).
__device__ __forceinline__ float reduce8(const float a_in[8], int lane) {
    float b[4];
    bool h1 = lane & 16;
    #pragma unroll
    for (int k = 0; k < 4; ++k) {
        float send = h1 ? a_in[k]     : a_in[k + 4];
        float keep = h1 ? a_in[k + 4] : a_in[k];
        b[k] = keep + __shfl_xor_sync(0xffffffffu, send, 16);
    }
    float c[2];
    bool h2 = lane & 8;
    #pragma unroll
    for (int k = 0; k < 2; ++k) {
        float send = h2 ? b[k]     : b[k + 2];
        float keep = h2 ? b[k + 2] : b[k];
        c[k] = keep + __shfl_xor_sync(0xffffffffu, send, 8);
    }
    bool h3 = lane & 4;
    float send = h3 ? c[0] : c[1];
    float keep = h3 ? c[1] : c[0];
    float d = keep + __shfl_xor_sync(0xffffffffu, send, 4);
    d += __shfl_xor_sync(0xffffffffu, d, 2);
    d += __shfl_xor_sync(0xffffffffu, d, 1);
    return d;
}

__device__ __forceinline__ void pdl_trigger() {
    asm volatile("griddepcontrol.launch_dependents;" ::: "memory");
}
__device__ __forceinline__ void pdl_wait() {
    asm volatile("griddepcontrol.wait;" ::: "memory");
}

// ---------------- K1: prep + corrections (his: 1 entry/warp for minimum serial depth) ----------------
__global__ __launch_bounds__(256)
void k1_kernel(const int* __restrict__ now_nodes,
               const int* __restrict__ his_nodes,
               const float* __restrict__ alpha,
               const float* __restrict__ station_embedding,
               const float* __restrict__ raw_field_embed,
               const float* __restrict__ w_st,
               const float* __restrict__ w_his1,
               const float* __restrict__ b_his1,
               const float* __restrict__ w_his2,
               const float* __restrict__ b_his2,
               const float* __restrict__ proj_w,
               const float* __restrict__ proj_b,
               const float* __restrict__ w_u,
               const float* __restrict__ b_u,
               const float* __restrict__ b_st,
               const float* __restrict__ user_embedding,
               const float* __restrict__ user_emb_table,
               const float* __restrict__ theta,
               const int* __restrict__ user_id,
               int Bn, int N, int K, int BK, int hisBlocks, int nowBlocks)
{
    int tid  = threadIdx.x;
    int lane = tid & 31, warp = tid >> 5;

    if (blockIdx.x < (unsigned)hisBlocks) {
        // ---- his MLP: 8 entries per block, ONE entry per warp ----
        __shared__ float w1s[128 * 64];     // 32 KB
        __shared__ float xs[8][128];        // 4 KB
        __shared__ float us[64];
        __shared__ float sh_bh2;

        // stage all of w_his1 into registers (one DRAM/L2 round)
        float4 wreg[8];
        #pragma unroll
        for (int i = 0; i < 8; ++i)
            wreg[i] = reinterpret_cast<const float4*>(w_his1)[tid + i * 256];

        int e0 = blockIdx.x * 8 + warp;
        bool v0 = e0 < BK;
        int n0 = v0 ? his_nodes[e0] : 0;
        float4 x0 = v0 ? reinterpret_cast<const float4*>(raw_field_embed + (size_t)n0 * 128)[lane]
                       : make_float4(0.f,0.f,0.f,0.f);

        // u[j] = w_his2[j,:]·w_st : 8 warps x 8 rows, one round
        float4 wv = reinterpret_cast<const float4*>(w_st)[lane];
        {
            int r0 = warp * 8;
            float a[8];
            #pragma unroll
            for (int i = 0; i < 8; ++i) {
                float4 r = reinterpret_cast<const float4*>(w_his2 + (r0 + i) * 128)[lane];
                a[i] = r.x * wv.x + r.y * wv.y + r.z * wv.z + r.w * wv.w;
            }
            float d = reduce8(a, lane);
            int row = ((lane >> 4) & 1) * 4 + ((lane >> 3) & 1) * 2 + ((lane >> 2) & 1);
            if ((lane & 3) == 0) us[r0 + row] = d;
        }
        if (warp == 0) {
            float4 bh = reinterpret_cast<const float4*>(b_his2)[lane];
            float p = warp_sum(bh.x * wv.x + bh.y * wv.y + bh.z * wv.z + bh.w * wv.w);
            if (lane == 0) sh_bh2 = p;
        }

        // commit staged weights + x row to smem
        #pragma unroll
        for (int i = 0; i < 8; ++i)
            reinterpret_cast<float4*>(w1s)[tid + i * 256] = wreg[i];
        reinterpret_cast<float4*>(&xs[warp][0])[lane] = x0;
        __syncthreads();

        float a0 = b_his1[lane], a1 = b_his1[lane + 32];
        const float* xp0 = &xs[warp][0];
        #pragma unroll 8
        for (int d = 0; d < 128; ++d) {
            float x = xp0[d];
            a0 += x * w1s[d * 64 + lane];
            a1 += x * w1s[d * 64 + lane + 32];
        }
        float u0 = us[lane], u1 = us[lane + 32], bh2 = sh_bh2;
        float l = (a0 > 0.f ? a0 : 0.01f * a0) * u0 + (a1 > 0.f ? a1 : 0.01f * a1) * u1;
        float val0 = warp_sum(l);
        if (lane == 0 && v0) {
            int b = e0 / K;
            atomicAdd(&g_delta[(size_t)b * N + n0], alpha[n0] * (val0 + bh2));
            atomicOr(&g_flag[n0], 1u << b);
        }
    } else if (blockIdx.x < (unsigned)(hisBlocks + nowBlocks)) {
        // ---- now dot entries: prefetch 4 rows, then reduce ----
        int bb = blockIdx.x - hisBlocks;
        float4 w4 = reinterpret_cast<const float4*>(w_st)[lane];
        int   ns[4]; int bsv[4]; bool vv[4];
        float4 r[4];
        #pragma unroll
        for (int i = 0; i < 4; ++i) {
            int e = bb * 32 + warp * 4 + i;
            vv[i] = e < BK;
            ns[i] = vv[i] ? now_nodes[e] : 0;
            bsv[i] = vv[i] ? e / K : 0;
            r[i] = vv[i]
                 ? reinterpret_cast<const float4*>(station_embedding + (size_t)ns[i] * 128)[lane]
                 : make_float4(0.f,0.f,0.f,0.f);
        }
        #pragma unroll
        for (int i = 0; i < 4; ++i) {
            float p = warp_sum(r[i].x * w4.x + r[i].y * w4.y + r[i].z * w4.z + r[i].w * w4.w);
            if (lane == 0 && vv[i]) {
                atomicAdd(&g_delta[(size_t)bsv[i] * N + ns[i]], alpha[ns[i]] * p);
                atomicOr(&g_flag[ns[i]], 1u << bsv[i]);
            }
        }
    } else {
        // ---- prep: g_v (16 rows/warp, one round), g_U, g_c ----
        float4 wv = reinterpret_cast<const float4*>(w_st)[lane];
        {
            int r0 = warp * 16;
            float4 rr[16];
            #pragma unroll
            for (int i = 0; i < 16; ++i)
                rr[i] = reinterpret_cast<const float4*>(proj_w + (r0 + i) * 128)[lane];
            float a[8];
            #pragma unroll
            for (int i = 0; i < 8; ++i)
                a[i] = rr[i].x * wv.x + rr[i].y * wv.y + rr[i].z * wv.z + rr[i].w * wv.w;
            float d = reduce8(a, lane);
            int row = ((lane >> 4) & 1) * 4 + ((lane >> 3) & 1) * 2 + ((lane >> 2) & 1);
            if ((lane & 3) == 0) g_v[r0 + row] = d;
            #pragma unroll
            for (int i = 0; i < 8; ++i)
                a[i] = rr[i+8].x * wv.x + rr[i+8].y * wv.y + rr[i+8].z * wv.z + rr[i+8].w * wv.w;
            d = reduce8(a, lane);
            if ((lane & 3) == 0) g_v[r0 + 8 + row] = d;
        }
        int b = warp;
        if (b < Bn) {
            int uid = user_id[b];
            float th = theta[uid];
            float4 ue = reinterpret_cast<const float4*>(user_embedding + b * 128)[lane];
            float4 ut = reinterpret_cast<const float4*>(user_emb_table + (size_t)uid * 128)[lane];
            float4 wu = reinterpret_cast<const float4*>(w_u)[lane];
            float p = ((1.f - th) * ue.x + th * ut.x) * wu.x
                    + ((1.f - th) * ue.y + th * ut.y) * wu.y
                    + ((1.f - th) * ue.z + th * ut.z) * wu.z
                    + ((1.f - th) * ue.w + th * ut.w) * wu.w;
            p = warp_sum(p);
            if (lane == 0) g_U[b] = p + b_u[0] + b_st[0];
        }
        if (warp == 0) {
            float4 pb = reinterpret_cast<const float4*>(proj_b)[lane];
            float p = warp_sum(pb.x * wv.x + pb.y * wv.y + pb.z * wv.z + pb.w * wv.w);
            if (lane == 0) g_c = p;
        }
    }
    // all global writes for this CTA are done — allow the dependent sweep to launch
    pdl_trigger();
}

// ---------------- K2: main sweep (R10 shape; __ldcv table loads — the documented cap path) ------
__global__ __launch_bounds__(256)
void main_kernel(const float* __restrict__ set_table,
                 const float* __restrict__ alpha,
                 float* __restrict__ out, int N, int Bn)
{
    __shared__ float    sh_s[64];
    __shared__ unsigned sh_f[64];
    __shared__ float    sh_U[16];
    int tid = threadIdx.x;
    int lane = tid & 31, warp = tid >> 5;
    int base = blockIdx.x * 64;

    // issue the 8 row loads FIRST — independent of k1, overlaps with k1 completion.
    // __ldcv: fetch-from-memory path (LDG.cv), the documented 6300 B/cyc configuration.
    int n0 = base + warp * 8;
    float4 r[8];
    #pragma unroll
    for (int i = 0; i < 8; ++i) {
        int n = n0 + i;
        r[i] = (n < N)
             ? __ldcv(reinterpret_cast<const float4*>(set_table + (size_t)n * 128) + lane)
             : make_float4(0.f, 0.f, 0.f, 0.f);
    }

    pdl_wait();   // k1's g_v/g_U/g_c/g_flag/g_delta now visible

    if (tid < Bn) sh_U[tid] = g_U[tid];
    if (tid < 64) {
        int n = base + tid;
        unsigned f = (n < N) ? g_flag[n] : 0u;
        sh_f[tid] = f;
        if (f) g_flag[n] = 0u;                 // one-shot restore for next replay
    }
    float4 v4 = reinterpret_cast<const float4*>(g_v)[lane];
    float cval = g_c;

    float a[8];
    #pragma unroll
    for (int i = 0; i < 8; ++i)
        a[i] = r[i].x * v4.x + r[i].y * v4.y + r[i].z * v4.z + r[i].w * v4.w;
    float s = reduce8(a, lane) + cval;
    int rowm = ((lane >> 4) & 1) * 4 + ((lane >> 3) & 1) * 2 + ((lane >> 2) & 1);
    if ((lane & 3) == 0) sh_s[warp * 8 + rowm] = s;
    __syncthreads();

    int count = N - base; if (count > 64) count = 64;

    if (Bn == 8 && (N & 1) == 0) {
        // fast path: 256 threads = 8 rows x 32 float2 streaming stores
        int b = tid >> 5, j = (tid & 31) * 2;
        if (j < count) {
            int n = base + j;
            float Ub = sh_U[b];
            float s0 = sh_s[j];
            unsigned f0 = sh_f[j];
            float v0 = s0 + Ub;
            if ((f0 >> b) & 1u) {
                v0 = (1.f - alpha[n]) * s0 + Ub + g_delta[(size_t)b * N + n];
                g_delta[(size_t)b * N + n] = 0.f;
            }
            if (j + 1 < count) {
                float s1 = sh_s[j + 1];
                unsigned f1 = sh_f[j + 1];
                float v1 = s1 + Ub;
                if ((f1 >> b) & 1u) {
                    v1 = (1.f - alpha[n + 1]) * s1 + Ub + g_delta[(size_t)b * N + n + 1];
                    g_delta[(size_t)b * N + n + 1] = 0.f;
                }
                __stcs(reinterpret_cast<float2*>(out + (size_t)b * N + n), make_float2(v0, v1));
            } else {
                out[(size_t)b * N + n] = v0;
            }
        }
    } else {
        // generic fallback
        for (int idx = tid; idx < Bn * 64; idx += 256) {
            int b = idx >> 6, j = idx & 63;
            if (j < count) {
                int n = base + j;
                float s0 = sh_s[j];
                float val = s0 + sh_U[b];
                unsigned f = sh_f[j];
                if ((f >> b) & 1u) {
                    val = (1.f - alpha[n]) * s0 + sh_U[b] + g_delta[(size_t)b * N + n];
                    g_delta[(size_t)b * N + n] = 0.f;
                }
                out[(size_t)b * N + n] = val;
            }
        }
    }
}

// ---------------- host launch ----------------
extern "C" void kernel_launch(void* const* d_in, const int* in_sizes, int n_in,
                              void* d_out, int out_size)
{
    int iUE, iSE, iRFE, iHIS, iNOW, iUID, iUET, iSET, iPW, iPB, iTH, iAL,
        iW1, iB1, iW2, iB2, iWST, iBST, iWU, iBU;
    if (in_sizes[3] < 100000) {
        iUE=0; iSE=1; iRFE=2; iHIS=3; iNOW=4; iUID=5; iUET=6; iSET=7; iPW=8; iPB=9;
        iTH=10; iAL=11; iW1=12; iB1=13; iW2=14; iB2=15; iWST=16; iBST=17; iWU=18; iBU=19;
    } else {
        iUE=0; iSE=1; iRFE=2; iUET=3; iSET=4; iPW=5; iPB=6; iTH=7; iAL=8; iW1=9;
        iB1=10; iW2=11; iB2=12; iWST=13; iBST=14; iWU=15; iBU=16; iHIS=17; iNOW=18; iUID=19;
    }

    const float* user_embedding    = (const float*)d_in[iUE];
    const float* station_embedding = (const float*)d_in[iSE];
    const float* raw_field_embed   = (const float*)d_in[iRFE];
    const float* user_emb_table    = (const float*)d_in[iUET];
    const float* station_emb_table = (const float*)d_in[iSET];
    const float* proj_w            = (const float*)d_in[iPW];
    const float* proj_b            = (const float*)d_in[iPB];
    const float* theta             = (const float*)d_in[iTH];
    const float* alpha             = (const float*)d_in[iAL];
    const float* w_his1            = (const float*)d_in[iW1];
    const float* b_his1            = (const float*)d_in[iB1];
    const float* w_his2            = (const float*)d_in[iW2];
    const float* b_his2            = (const float*)d_in[iB2];
    const float* w_st              = (const float*)d_in[iWST];
    const float* b_st              = (const float*)d_in[iBST];
    const float* w_u               = (const float*)d_in[iWU];
    const float* b_u               = (const float*)d_in[iBU];
    const int*   his_nodes         = (const int*)d_in[iHIS];
    const int*   now_nodes         = (const int*)d_in[iNOW];
    const int*   user_id           = (const int*)d_in[iUID];

    int B  = in_sizes[iUE] / 128;     // 8
    int N  = in_sizes[iAL];           // 60082
    int BK = in_sizes[iHIS];          // 256
    int K  = BK / B;                  // 32

    float* out = (float*)d_out;
    (void)out_size; (void)n_in;

    int hisBlocks = (BK + 7) / 8;     // 32 blocks, 1 entry/warp
    int nowBlocks = (BK + 31) / 32;   // 8 blocks
    k1_kernel<<<hisBlocks + nowBlocks + 1, 256>>>(
        now_nodes, his_nodes, alpha, station_embedding, raw_field_embed,
        w_st, w_his1, b_his1, w_his2, b_his2, proj_w, proj_b,
        w_u, b_u, b_st, user_embedding, user_emb_table, theta, user_id,
        B, N, K, BK, hisBlocks, nowBlocks);

    // main with programmatic dependent launch — overlaps its load ramp with k1 tail
    int grid = (N + 63) / 64;
    cudaLaunchConfig_t cfg = {};
    cfg.gridDim  = dim3((unsigned)grid, 1, 1);
    cfg.blockDim = dim3(256, 1, 1);
    cfg.dynamicSmemBytes = 0;
    cfg.stream = 0;
    cudaLaunchAttribute attr[1];
    attr[0].id = cudaLaunchAttributeProgrammaticStreamSerialization;
    attr[0].val.programmaticStreamSerializationAllowed = 1;
    cfg.attrs = attr;
    cfg.numAttrs = 1;
    cudaLaunchKernelEx(&cfg, main_kernel, station_emb_table, alpha, out, N, B);
}